// round 13
// baseline (speedup 1.0000x reference)
#include <cuda_runtime.h>
#include <math.h>

#define SEQ   128
#define BATCH 512
#define INDIM 128
#define HID   128
#define FULLM 0xffffffffu

__device__ __forceinline__ float sigmoid_f(float x) {
    return __fdividef(1.f, 1.f + __expf(-x));
}
__device__ __forceinline__ float tanh_f(float x) {
    return 1.f - 2.f * __fdividef(1.f, 1.f + __expf(2.f * x));
}

struct C2 { float re, im; };
__device__ __forceinline__ C2 cmul(C2 a, C2 b) {
    return { a.re * b.re - a.im * b.im, a.re * b.im + a.im * b.re };
}

// 512 blocks (one per batch element), 256 threads = 8 warps.
// Warp wp = (comp, g): g = wp&3 gate type (f,i,g,o), comp = wp>>2 real/imag.
// Algebraic folds:
//  - RY(layer0)*RX(enc)|0> is a product state (closed form, no sim).
//  - CNOT ladder 1 folded into the init via Gray-coded selects:
//      v[i] = psi1[i ^ (i>>1)],  bit_m(i^(i>>1)) = bit_m(i)^bit_{m+1}(i)
//    -> zero shuffles for state prep.
//  - CNOT ladder 2 folded into measurement parity signs.
__global__ __launch_bounds__(256, 4)
void qlstm_kernel(const float* __restrict__ inputs,
                  const float* __restrict__ Wq,  const float* __restrict__ bq,
                  const float* __restrict__ pf,  const float* __restrict__ pi_,
                  const float* __restrict__ pg,  const float* __restrict__ po,
                  const float* __restrict__ Wfp, const float* __restrict__ bf,
                  const float* __restrict__ Wip, const float* __restrict__ bi,
                  const float* __restrict__ Wgp, const float* __restrict__ bg,
                  const float* __restrict__ Wop, const float* __restrict__ bo,
                  float* __restrict__ out)
{
    __shared__ __align__(16) float sWq[8][256];
    __shared__ __align__(16) float sWT2[4][128][12];  // [g][hd][w<8], pad 12 => conflict-free LDS.128
    __shared__ __align__(16) float sb2[128][4];       // [hd][g]
    __shared__ float sbq[8];
    __shared__ float rc[4][2][8], rs[4][2][8];
    __shared__ __align__(16) float comb[256];         // [ x_t | h ]
    __shared__ float cth[8], sth[8];                  // RX half-angle cos/sin
    __shared__ __align__(16) float zz2[2][4][8];      // [comp][g][w]

    const int tid  = threadIdx.x;
    const int lane = tid & 31;
    const int wp   = tid >> 5;
    const int g    = wp & 3;
    const int comp = wp >> 2;
    const int b    = blockIdx.x;

    // ---- stage weights ----
    for (int i = tid; i < 8 * 256; i += 256) sWq[i >> 8][i & 255] = Wq[i];
    {
        const float* W4[4] = {Wfp, Wip, Wgp, Wop};
        const float* b4[4] = {bf, bi, bg, bo};
        const float* p4[4] = {pf, pi_, pg, po};
        for (int gg = 0; gg < 4; gg++) {
            for (int i = tid; i < 1024; i += 256) sWT2[gg][i >> 3][i & 7] = W4[gg][i];
            if (tid < 128) sb2[tid][gg] = b4[gg][tid];
            if (tid < 16) {
                float a = 0.5f * p4[gg][tid];
                rc[gg][tid >> 3][tid & 7] = cosf(a);
                rs[gg][tid >> 3][tid & 7] = sinf(a);
            }
        }
    }
    if (tid < 8) sbq[tid] = bq[tid];
    if (tid < 128) comb[128 + tid] = 0.f;                                      // h0
    else           comb[tid - 128] = inputs[(size_t)b * INDIM + (tid - 128)];  // x_0
    float c_reg = 0.f;
    __syncthreads();

    const int glane = lane ^ (lane >> 1);
    const int L4    = (lane >> 4) & 1;

    for (int t = 0; t < SEQ; t++) {
        // ---- phase B: q_in row = wp (vectorized dot) ----
        {
            const float4* c4 = (const float4*)comb;
            const float4* w4 = (const float4*)sWq[wp];
            const float4 a0 = c4[lane],      b0 = w4[lane];
            const float4 a1 = c4[lane + 32], b1 = w4[lane + 32];
            float sum = a0.x * b0.x;
            sum = fmaf(a0.y, b0.y, sum); sum = fmaf(a0.z, b0.z, sum);
            sum = fmaf(a0.w, b0.w, sum); sum = fmaf(a1.x, b1.x, sum);
            sum = fmaf(a1.y, b1.y, sum); sum = fmaf(a1.z, b1.z, sum);
            sum = fmaf(a1.w, b1.w, sum);
            #pragma unroll
            for (int off = 16; off; off >>= 1)
                sum += __shfl_xor_sync(FULLM, sum, off);
            if (lane == 0) {
                float a = 0.5f * (sum + sbq[wp]);
                float s, c;
                __sincosf(a, &s, &c);
                cth[wp] = c; sth[wp] = s;
            }
        }
        __syncthreads();

        // ---- phase C: statevector sim ----
        {
            float v[8];
            // per-wire factors: f_w(0)=(cp*ct, sp*st), f_w(1)=(sp*ct, -cp*st)
            // Gray-coded init = product state with CNOT1 pre-applied.
            C2 com = {1.f, 0.f};
            #pragma unroll
            for (int k = 0; k < 4; k++) {              // wires 7,6,5,4 (lane Gray bits)
                const int w = 7 - k;
                const float cp = rc[g][0][w], sp = rs[g][0][w];
                const float ct = cth[w],      st = sth[w];
                const int bit = (glane >> k) & 1;
                const C2 f = { (bit ? sp : cp) * ct,
                               bit ? -(cp * st) : (sp * st) };
                com = cmul(com, f);
            }
            C2 A[2];                                    // wire 3: sel = L4 ^ (r&1)
            {
                const float cp = rc[g][0][3], sp = rs[g][0][3];
                const float ct = cth[3],      st = sth[3];
                const C2 f0 = { cp * ct,  sp * st };
                const C2 f1 = { sp * ct, -cp * st };
                A[0] = cmul(com, L4 ? f1 : f0);
                A[1] = cmul(com, L4 ? f0 : f1);
            }
            C2 F2[2], F1[2], F0[2];                     // register wires 2,1,0
            {
                float cp, sp, ct, st;
                cp = rc[g][0][2]; sp = rs[g][0][2]; ct = cth[2]; st = sth[2];
                F2[0] = { cp * ct,  sp * st }; F2[1] = { sp * ct, -cp * st };
                cp = rc[g][0][1]; sp = rs[g][0][1]; ct = cth[1]; st = sth[1];
                F1[0] = { cp * ct,  sp * st }; F1[1] = { sp * ct, -cp * st };
                cp = rc[g][0][0]; sp = rs[g][0][0]; ct = cth[0]; st = sth[0];
                F0[0] = { cp * ct,  sp * st }; F0[1] = { sp * ct, -cp * st };
            }
            const C2 h00 = cmul(F1[0], F0[0]);
            const C2 h01 = cmul(F1[1], F0[1]);
            const C2 h10 = cmul(F1[1], F0[0]);
            const C2 h11 = cmul(F1[0], F0[1]);
            #pragma unroll
            for (int r = 0; r < 8; r++) {
                const int R0 = r & 1, R1 = (r >> 1) & 1, R2 = (r >> 2) & 1;
                const C2 hh = R1 ? (R2 ? h11 : h10) : (R2 ? h01 : h00);
                const C2 P  = cmul(F2[R0 ^ R1], hh);
                const C2 Aa = A[R0];
                v[r] = (comp == 0) ? (Aa.re * P.re - Aa.im * P.im)
                                   : (Aa.re * P.im + Aa.im * P.re);
            }

            // RY layer 2 (all wires commute; CNOT1 already folded into init)
            #pragma unroll
            for (int w = 0; w < 8; w++) {
                const float c = rc[g][1][w], s = rs[g][1][w];
                if (w <= 2) {
                    const int rb = 2 - w;
                    #pragma unroll
                    for (int r0 = 0; r0 < 8; r0++) {
                        if (!((r0 >> rb) & 1)) {
                            const int r1 = r0 | (1 << rb);
                            const float a0 = v[r0], a1 = v[r1];
                            v[r0] = fmaf(c, a0, -s * a1);
                            v[r1] = fmaf(s, a0,  c * a1);
                        }
                    }
                } else {
                    const int pb = 7 - w;
                    const int m = 1 << pb;
                    const float sg = ((lane >> pb) & 1) ? s : -s;
                    #pragma unroll
                    for (int r = 0; r < 8; r++) {
                        const float pv = __shfl_xor_sync(FULLM, v[r], m);
                        v[r] = fmaf(c, v[r], sg * pv);
                    }
                }
            }

            // measurement (CNOT ladder 2 folded into signs)
            float p[8];
            #pragma unroll
            for (int r = 0; r < 8; r++) p[r] = v[r] * v[r];

            float d0 = ((p[0] - p[1]) - (p[2] - p[3])) - ((p[4] - p[5]) - (p[6] - p[7]));
            float a0 = (p[0] + p[1] + p[2] + p[3]) - (p[4] + p[5] + p[6] + p[7]);
            float a1 = (p[0] + p[1] + p[6] + p[7]) - (p[2] + p[3] + p[4] + p[5]);

            #pragma unroll
            for (int off = 16; off; off >>= 1) {
                a0 += __shfl_xor_sync(FULLM, a0, off);
                a1 += __shfl_xor_sync(FULLM, a1, off);
            }
            #pragma unroll
            for (int k = 0; k < 5; k++) {
                const float pv = __shfl_xor_sync(FULLM, d0, 1 << k);
                d0 = ((lane >> k) & 1) ? pv - d0 : pv + d0;
            }
            if (lane == 0)  { zz2[comp][g][0] = a0; zz2[comp][g][1] = a1; zz2[comp][g][2] = d0; }
            if (lane == 16)   zz2[comp][g][3] = d0;
            if (lane == 24)   zz2[comp][g][4] = d0;
            if (lane == 28)   zz2[comp][g][5] = d0;
            if (lane == 30)   zz2[comp][g][6] = d0;
            if (lane == 31)   zz2[comp][g][7] = d0;
        }
        __syncthreads();

        // ---- phase D (warps 0-3, vectorized) || x prefetch (warp 4) ----
        if (tid < 128) {
            const int hd = tid;
            const float4 bb = *(const float4*)sb2[hd];
            float acc[4] = { bb.x, bb.y, bb.z, bb.w };
            const float4* zzv = (const float4*)zz2;   // [comp][g] -> 2 vec4 each
            #pragma unroll
            for (int gg = 0; gg < 4; gg++) {
                const float4 zr0 = zzv[gg * 2 + 0],     zr1 = zzv[gg * 2 + 1];
                const float4 zi0 = zzv[8 + gg * 2 + 0], zi1 = zzv[8 + gg * 2 + 1];
                const float4 w0 = *(const float4*)&sWT2[gg][hd][0];
                const float4 w1 = *(const float4*)&sWT2[gg][hd][4];
                float a = acc[gg];
                a = fmaf(w0.x, zr0.x + zi0.x, a);
                a = fmaf(w0.y, zr0.y + zi0.y, a);
                a = fmaf(w0.z, zr0.z + zi0.z, a);
                a = fmaf(w0.w, zr0.w + zi0.w, a);
                a = fmaf(w1.x, zr1.x + zi1.x, a);
                a = fmaf(w1.y, zr1.y + zi1.y, a);
                a = fmaf(w1.z, zr1.z + zi1.z, a);
                a = fmaf(w1.w, zr1.w + zi1.w, a);
                acc[gg] = a;
            }
            const float f  = sigmoid_f(acc[0]);
            const float ii = sigmoid_f(acc[1]);
            const float gg = tanh_f(acc[2]);
            const float oo = sigmoid_f(acc[3]);
            const float cn = fmaf(f, c_reg, ii * gg);
            const float hn = oo * tanh_f(cn);
            out[((size_t)t * BATCH + b) * HID + hd] = hn;
            c_reg = cn;
            comb[128 + hd] = hn;
        } else if (wp == 4 && t + 1 < SEQ) {
            const float4* ip = (const float4*)(inputs + ((size_t)(t + 1) * BATCH + b) * INDIM);
            ((float4*)comb)[lane] = ip[lane];
        }
        __syncthreads();
    }

    if (tid < 128) {
        out[(size_t)SEQ * BATCH * HID + (size_t)b * HID + tid]                       = comb[128 + tid];
        out[(size_t)SEQ * BATCH * HID + (size_t)BATCH * HID + (size_t)b * HID + tid] = c_reg;
    }
}

extern "C" void kernel_launch(void* const* d_in, const int* in_sizes, int n_in,
                              void* d_out, int out_size) {
    const float* inputs = (const float*)d_in[0];
    const float* Wq  = (const float*)d_in[1];
    const float* bq  = (const float*)d_in[2];
    const float* pf  = (const float*)d_in[3];
    const float* pi_ = (const float*)d_in[4];
    const float* pg  = (const float*)d_in[5];
    const float* po  = (const float*)d_in[6];
    const float* Wf  = (const float*)d_in[7];
    const float* bf  = (const float*)d_in[8];
    const float* Wi  = (const float*)d_in[9];
    const float* bi  = (const float*)d_in[10];
    const float* Wg  = (const float*)d_in[11];
    const float* bg  = (const float*)d_in[12];
    const float* Wo  = (const float*)d_in[13];
    const float* bo  = (const float*)d_in[14];

    qlstm_kernel<<<BATCH, 256>>>(inputs, Wq, bq, pf, pi_, pg, po,
                                 Wf, bf, Wi, bi, Wg, bg, Wo, bo,
                                 (float*)d_out);
}

// round 15
// speedup vs baseline: 3.0965x; 3.0965x over previous
#include <cuda_runtime.h>
#include <math.h>

#define SEQ   128
#define BATCH 512
#define INDIM 128
#define HID   128
#define FULLM 0xffffffffu

__device__ __forceinline__ float sigmoid_f(float x) {
    return __fdividef(1.f, 1.f + __expf(-x));
}
__device__ __forceinline__ float tanh_f(float x) {
    return 1.f - 2.f * __fdividef(1.f, 1.f + __expf(2.f * x));
}

// 512 blocks (one per batch element), 128 threads (4 warps).
// The quantum circuit is evaluated in CLOSED FORM via a Bloch-space transfer
// chain (MPS bond dim 2 -> 4-real transfer vector):
//   psi = RY2 * C1 * (prod_w RY(p0_w) RX(theta_w)|0>),  C2' Z_w C2 = Z_0..Z_w
//   per wire: delta=cos(p0)cos(th), rho=sin(p0)cos(th), eta=sin(th),
//             c=cos(p1), s=sin(p1):
//     t1=t+rho*x; x1=x+rho*t; y1=delta*y-eta*z; z1=delta*z+eta*y
//     t=c*z1; z=c*t1; x=-s*x1; y=-s*y1
//   <Z_{w-1}> = t1 computed at site w;  <Z_7> = t+x after site 7.
// (Verified analytically: zero-angle, theta0=pi cascade, theta1=pi/2 entangler.)
__global__ __launch_bounds__(128, 8)
void qlstm_kernel(const float* __restrict__ inputs,
                  const float* __restrict__ Wq,  const float* __restrict__ bq,
                  const float* __restrict__ pf,  const float* __restrict__ pi_,
                  const float* __restrict__ pg,  const float* __restrict__ po,
                  const float* __restrict__ Wfp, const float* __restrict__ bf,
                  const float* __restrict__ Wip, const float* __restrict__ bi,
                  const float* __restrict__ Wgp, const float* __restrict__ bg,
                  const float* __restrict__ Wop, const float* __restrict__ bo,
                  float* __restrict__ out)
{
    __shared__ __align__(16) float sWq[8][256];
    __shared__ float sWT[4][8][128];   // scalar layout: lane-consecutive hd, conflict-free
    __shared__ float sb[4][128];
    __shared__ float sbq[8];
    __shared__ float cons[4][8][4];    // {cos p0, sin p0, cos p1, sin p1} (FULL angles)
    __shared__ __align__(16) float comb[256];   // [ x_t | h ]
    __shared__ float cth[8], sth[8];   // FULL-angle cos/sin of theta_w
    __shared__ float zz[4][8];         // <Z_w> per gate

    const int tid  = threadIdx.x;
    const int lane = tid & 31;
    const int wp   = tid >> 5;
    const int b    = blockIdx.x;

    // ---- stage weights ----
    for (int i = tid; i < 2048; i += 128) sWq[i >> 8][i & 255] = Wq[i];
    {
        const float* W4[4] = {Wfp, Wip, Wgp, Wop};
        const float* b4[4] = {bf, bi, bg, bo};
        const float* p4[4] = {pf, pi_, pg, po};
        for (int g = 0; g < 4; g++) {
            for (int i = tid; i < 1024; i += 128) sWT[g][i & 7][i >> 3] = W4[g][i];
            sb[g][tid] = b4[g][tid];
        }
        if (tid < 32) {
            const int g = tid >> 3, w = tid & 7;
            const float p0 = p4[g][w];        // params[0][w]
            const float p1 = p4[g][8 + w];    // params[1][w]
            cons[g][w][0] = cosf(p0);
            cons[g][w][1] = sinf(p0);
            cons[g][w][2] = cosf(p1);
            cons[g][w][3] = sinf(p1);
        }
    }
    if (tid < 8) sbq[tid] = bq[tid];
    comb[tid]       = inputs[(size_t)b * INDIM + tid];  // x_0
    comb[128 + tid] = 0.f;                              // h_0
    float c_reg = 0.f;
    __syncthreads();

    // chain constants in registers for the 4 chain threads
    float cp0r[8], sp0r[8], cb1r[8], sb1r[8];
    if (tid < 4) {
        #pragma unroll
        for (int w = 0; w < 8; w++) {
            cp0r[w] = cons[tid][w][0];
            sp0r[w] = cons[tid][w][1];
            cb1r[w] = cons[tid][w][2];
            sb1r[w] = cons[tid][w][3];
        }
    }

    const int row = wp * 2 + (lane >> 4);   // warp handles rows 2wp, 2wp+1 (16 lanes each)
    const int sub = lane & 15;

    for (int t = 0; t < SEQ; t++) {
        // ---- phase B: theta_row = Wq[row].comb + bq[row]; full-angle sincos ----
        {
            const float4* c4 = (const float4*)comb;
            const float4* w4 = (const float4*)sWq[row];
            float sum = 0.f;
            #pragma unroll
            for (int k = 0; k < 4; k++) {
                const float4 a  = c4[sub + 16 * k];
                const float4 ww = w4[sub + 16 * k];
                sum = fmaf(a.x, ww.x, sum); sum = fmaf(a.y, ww.y, sum);
                sum = fmaf(a.z, ww.z, sum); sum = fmaf(a.w, ww.w, sum);
            }
            sum += __shfl_xor_sync(FULLM, sum, 8);
            sum += __shfl_xor_sync(FULLM, sum, 4);
            sum += __shfl_xor_sync(FULLM, sum, 2);
            sum += __shfl_xor_sync(FULLM, sum, 1);
            if (sub == 0) {
                const float th = sum + sbq[row];
                float s, c;
                __sincosf(th, &s, &c);
                cth[row] = c; sth[row] = s;
            }
        }
        __syncthreads();

        // prefetch x_{t+1} (LDG latency hidden across the chain barrier)
        float xn = 0.f;
        if (t + 1 < SEQ) xn = inputs[((size_t)(t + 1) * BATCH + b) * INDIM + tid];

        // ---- phase C: Bloch transfer chain, thread tid = gate tid (0..3) ----
        if (tid < 4) {
            float T = 1.f, X = 0.f, Y = 0.f, Z = 1.f;
            #pragma unroll
            for (int w = 0; w < 8; w++) {
                const float cw  = cth[w], sw = sth[w];
                const float rho = sp0r[w] * cw;
                const float del = cp0r[w] * cw;
                const float t1 = fmaf(rho, X, T);
                const float x1 = fmaf(rho, T, X);
                const float y1 = fmaf(del, Y, -sw * Z);
                const float z1 = fmaf(sw, Y, del * Z);
                if (w) zz[tid][w - 1] = t1;        // <Z_{w-1}> readout is free
                T = cb1r[w] * z1;
                Z = cb1r[w] * t1;
                X = -sb1r[w] * x1;
                Y = -sb1r[w] * y1;
            }
            zz[tid][7] = T + X;
        }
        __syncthreads();

        // ---- phase D: gate GEMVs + LSTM pointwise, thread = hidden unit ----
        {
            const int hd = tid;
            float a0 = sb[0][hd], a1 = sb[1][hd], a2 = sb[2][hd], a3 = sb[3][hd];
            #pragma unroll
            for (int w = 0; w < 8; w++) {
                a0 = fmaf(sWT[0][w][hd], zz[0][w], a0);
                a1 = fmaf(sWT[1][w][hd], zz[1][w], a1);
                a2 = fmaf(sWT[2][w][hd], zz[2][w], a2);
                a3 = fmaf(sWT[3][w][hd], zz[3][w], a3);
            }
            const float f  = sigmoid_f(a0);
            const float ii = sigmoid_f(a1);
            const float gg = tanh_f(a2);
            const float oo = sigmoid_f(a3);
            const float cn = fmaf(f, c_reg, ii * gg);
            const float hn = oo * tanh_f(cn);
            out[((size_t)t * BATCH + b) * HID + hd] = hn;
            c_reg = cn;
            comb[128 + hd] = hn;   // h_{t+1} input
            comb[hd] = xn;         // x_{t+1} (phase B of this step already done)
        }
        __syncthreads();
    }

    // final hx, cx
    out[(size_t)SEQ * BATCH * HID + (size_t)b * HID + tid]                       = comb[128 + tid];
    out[(size_t)SEQ * BATCH * HID + (size_t)BATCH * HID + (size_t)b * HID + tid] = c_reg;
}

extern "C" void kernel_launch(void* const* d_in, const int* in_sizes, int n_in,
                              void* d_out, int out_size) {
    const float* inputs = (const float*)d_in[0];
    const float* Wq  = (const float*)d_in[1];
    const float* bq  = (const float*)d_in[2];
    const float* pf  = (const float*)d_in[3];
    const float* pi_ = (const float*)d_in[4];
    const float* pg  = (const float*)d_in[5];
    const float* po  = (const float*)d_in[6];
    const float* Wf  = (const float*)d_in[7];
    const float* bf  = (const float*)d_in[8];
    const float* Wi  = (const float*)d_in[9];
    const float* bi  = (const float*)d_in[10];
    const float* Wg  = (const float*)d_in[11];
    const float* bg  = (const float*)d_in[12];
    const float* Wo  = (const float*)d_in[13];
    const float* bo  = (const float*)d_in[14];

    qlstm_kernel<<<BATCH, 128>>>(inputs, Wq, bq, pf, pi_, pg, po,
                                 Wf, bf, Wi, bi, Wg, bg, Wo, bo,
                                 (float*)d_out);
}